// round 2
// baseline (speedup 1.0000x reference)
#include <cuda_runtime.h>
#include <cstdint>

// Problem constants
#define INC   32
#define INN   50000
#define OUTC  32
#define OUTN  8192
#define MAXD  16
#define NBATCH 8
#define NC    (NBATCH * INC)   // 256

// Scratch: transposed embedding table xt[INN][NC] (51.2 MB, fits in L2)
__device__ float g_xt[(size_t)INN * NC];

// ---------------------------------------------------------------------------
// Kernel 1: transpose x[256][50000] -> xt[50000][256]
// x flat index: (n*INC + c) * INN + i   ;   xt flat: i * 256 + (n*INC + c)
// 32x32 smem tile, 32x8 threads.
// ---------------------------------------------------------------------------
__global__ void transpose_kernel(const float* __restrict__ x) {
    __shared__ float tile[32][33];
    const int i0  = blockIdx.x * 32;
    const int nc0 = blockIdx.y * 32;
    const int tx = threadIdx.x;
    const int ty = threadIdx.y;

    #pragma unroll
    for (int r = ty; r < 32; r += 8) {
        const int nc = nc0 + r;
        const int i  = i0 + tx;
        tile[r][tx] = (i < INN) ? x[(size_t)nc * INN + i] : 0.0f;
    }
    __syncthreads();
    #pragma unroll
    for (int r = ty; r < 32; r += 8) {
        const int i = i0 + r;
        if (i < INN) {
            g_xt[(size_t)i * NC + nc0 + tx] = tile[tx][r];
        }
    }
}

// ---------------------------------------------------------------------------
// Kernel 2: per 32-node tile: gather+pool -> smem, then 32x32 matmul + bias,
// coalesced output writes.
//   pooled[o][nc] = sum_d mask[o][d] * xt[A[o][d]][nc]
//   y[n][d][o]    = sum_c pooled[o][n*32+c] * weight[c][d] + bias[d][o]
// ---------------------------------------------------------------------------
#define O_TILE 32

__global__ __launch_bounds__(256) void fgl_main_kernel(
    const int*   __restrict__ A,       // [OUTN][MAXD]
    const float* __restrict__ mask,    // [OUTN][MAXD]
    const float* __restrict__ weight,  // [INC][OUTC]
    const float* __restrict__ bias,    // [OUTC][OUTN]
    float*       __restrict__ y)       // [NBATCH][OUTC][OUTN]
{
    __shared__ float s_w[INC * OUTC];            // 4 KB
    __shared__ float s_pooled[O_TILE][NC + 1];   // 32 x 257 floats, padded
    __shared__ int   s_idx[O_TILE * MAXD];       // 512 ints
    __shared__ float s_msk[O_TILE * MAXD];       // 512 floats

    const int tid    = threadIdx.x;              // 0..255
    const int o_base = blockIdx.x * O_TILE;

    // Load weight (1024 floats -> 4 per thread)
    #pragma unroll
    for (int k = tid; k < INC * OUTC; k += 256) s_w[k] = weight[k];

    // Load adjacency + mask for this o-tile
    #pragma unroll
    for (int k = tid; k < O_TILE * MAXD; k += 256) {
        s_idx[k] = A[(size_t)o_base * MAXD + k];
        s_msk[k] = mask[(size_t)o_base * MAXD + k];
    }
    __syncthreads();

    // ---- Gather + pool phase (float4 vectorized) ----
    // thread -> (sub, q): sub = which of 4 concurrent o-rows, q = feature quad
    const int q   = tid & 63;   // 0..63 -> features [4q, 4q+3]
    const int sub = tid >> 6;   // 0..3
    #pragma unroll
    for (int ol0 = 0; ol0 < O_TILE; ol0 += 4) {
        const int ol = ol0 + sub;
        float4 acc = make_float4(0.f, 0.f, 0.f, 0.f);
        #pragma unroll
        for (int d = 0; d < MAXD; d++) {
            const int   idx = s_idx[ol * MAXD + d];
            const float m   = s_msk[ol * MAXD + d];
            const float4 v = *reinterpret_cast<const float4*>(
                g_xt + (size_t)idx * NC + q * 4);
            acc.x += m * v.x;
            acc.y += m * v.y;
            acc.z += m * v.z;
            acc.w += m * v.w;
        }
        // scalar stores into padded smem (row stride 257 keeps phase-2
        // column reads bank-conflict-free)
        s_pooled[ol][q * 4 + 0] = acc.x;
        s_pooled[ol][q * 4 + 1] = acc.y;
        s_pooled[ol][q * 4 + 2] = acc.z;
        s_pooled[ol][q * 4 + 3] = acc.w;
    }
    __syncthreads();

    // ---- Matmul + bias + coalesced store ----
    // Lane = output-node within tile (coalesced over o); loop over (n,d).
    const int o_lane = tid & 31;
    const int grp    = tid >> 5;      // 0..7
    const int o      = o_base + o_lane;

    #pragma unroll 4
    for (int j = 0; j < 32; j++) {
        const int nd = grp * 32 + j;  // 0..255
        const int n  = nd >> 5;
        const int d  = nd & 31;
        float acc = 0.0f;
        #pragma unroll
        for (int c = 0; c < INC; c++) {
            acc += s_pooled[o_lane][n * INC + c] * s_w[c * OUTC + d];
        }
        y[(size_t)n * (OUTC * OUTN) + (size_t)d * OUTN + o] =
            acc + bias[(size_t)d * OUTN + o];
    }
}

// ---------------------------------------------------------------------------
// Launch
// Inputs (metadata order): x [8,32,50000] f32, A [8192,16] i32,
//                          mask [8192,16,1] f32, weight [32,32] f32,
//                          bias [32,8192] f32. Output: [8,32,8192] f32.
// ---------------------------------------------------------------------------
extern "C" void kernel_launch(void* const* d_in, const int* in_sizes, int n_in,
                              void* d_out, int out_size) {
    const float* x      = (const float*)d_in[0];
    const int*   A      = (const int*)  d_in[1];
    const float* mask   = (const float*)d_in[2];
    const float* weight = (const float*)d_in[3];
    const float* bias   = (const float*)d_in[4];
    float*       y      = (float*)d_out;

    // Transpose x -> g_xt
    {
        dim3 grid((INN + 31) / 32, NC / 32);  // 1563 x 8
        dim3 block(32, 8);
        transpose_kernel<<<grid, block>>>(x);
    }
    // Main gather/pool/matmul
    {
        dim3 grid(OUTN / O_TILE);  // 256 blocks
        fgl_main_kernel<<<grid, 256>>>(A, mask, weight, bias, y);
    }
}

// round 3
// speedup vs baseline: 1.7167x; 1.7167x over previous
#include <cuda_runtime.h>
#include <cstdint>

// Problem constants
#define INC   32
#define INN   50000
#define OUTC  32
#define OUTN  8192
#define MAXD  16
#define NBATCH 8
#define NC    (NBATCH * INC)   // 256

// Scratch: transposed embedding table xt[INN][NC] (51.2 MB, L2-resident)
__device__ __align__(16) float g_xt[(size_t)INN * NC];
// Pooled intermediate [OUTN][NC] (8.4 MB)
__device__ __align__(16) float g_pooled[(size_t)OUTN * NC];

// ---------------------------------------------------------------------------
// Kernel 1: transpose x[256][50000] -> xt[50000][256], float4 both sides.
// Tile: 32 nc x 128 i. smem [32][129] (stride 129: conflict-free with the
// lane mappings below). Scalar STS/LDS inside smem; float4 LDG/STG outside.
// ---------------------------------------------------------------------------
#define TI 128

__global__ __launch_bounds__(256) void transpose_kernel(const float* __restrict__ x) {
    __shared__ float tile[32][129];
    const int i0  = blockIdx.x * TI;
    const int nc0 = blockIdx.y * 32;
    const int tid = threadIdx.x;

    // ---- Load phase ----
    // lane map: iq_low = tid&7 (i-quad), nc_low = (tid>>3)&3, warp = tid>>5.
    // Each warp: 4 nc rows x 8 quads (128B contiguous per row) -> coalesced.
    // STS bank = (nc_l + 4*iq + k) mod 32 with nc_l in 0..3, iq_low in 0..7:
    // distinct per lane -> conflict-free.
    {
        const int iq_low = tid & 7;
        const int nc_l   = ((tid >> 3) & 3) + 4 * (tid >> 5);   // 0..31
        const int nc     = nc0 + nc_l;
        #pragma unroll
        for (int r = 0; r < 4; r++) {
            const int iq = iq_low + 8 * r;        // 0..31
            const int i  = i0 + iq * 4;
            if (i < INN) {                        // INN%4==0 -> full quad ok
                const float4 v = *reinterpret_cast<const float4*>(
                    x + (size_t)nc * INN + i);
                tile[nc_l][iq * 4 + 0] = v.x;
                tile[nc_l][iq * 4 + 1] = v.y;
                tile[nc_l][iq * 4 + 2] = v.z;
                tile[nc_l][iq * 4 + 3] = v.w;
            }
        }
    }
    __syncthreads();

    // ---- Store phase ----
    // lane map: q = tid&7 (nc-quad), ib = tid>>3 (i within chunk, 0..31).
    // LDS bank = (4q + k + il) mod 32: 4q+il distinct for q 0..7, il%4 ->
    // conflict-free (stride 129). STG: per i row 8 float4 = 128B contiguous.
    {
        const int q  = tid & 7;
        const int ib = tid >> 3;                  // 0..31
        #pragma unroll
        for (int r = 0; r < 4; r++) {
            const int il = ib + 32 * r;           // 0..127
            const int i  = i0 + il;
            if (i < INN) {
                float4 v;
                v.x = tile[4 * q + 0][il];
                v.y = tile[4 * q + 1][il];
                v.z = tile[4 * q + 2][il];
                v.w = tile[4 * q + 3][il];
                *reinterpret_cast<float4*>(g_xt + (size_t)i * NC + nc0 + 4 * q) = v;
            }
        }
    }
}

// ---------------------------------------------------------------------------
// Kernel 2: gather + pool. One thread = (o, feature-quad).
//   pooled[o][nc] = sum_d mask[o][d] * xt[A[o][d]][nc]
// Block: 4 o x 64 quads = 256 threads. Warp = 32 consecutive quads of one o
// -> each gather LDG.128 is 512B contiguous within one xt row.
// 16 independent loads per thread (MLP=16), ~32 regs -> high occupancy.
// ---------------------------------------------------------------------------
__global__ __launch_bounds__(256) void gather_kernel(
    const int*   __restrict__ A,      // [OUTN][MAXD]
    const float* __restrict__ mask)   // [OUTN][MAXD]
{
    __shared__ int   s_idx[4 * MAXD];
    __shared__ float s_msk[4 * MAXD];

    const int tid    = threadIdx.x;
    const int q      = tid & 63;      // feature quad 0..63
    const int ol     = tid >> 6;      // 0..3
    const int o_base = blockIdx.x * 4;

    if (tid < 4 * MAXD) {
        s_idx[tid] = A[(size_t)o_base * MAXD + tid];
        s_msk[tid] = mask[(size_t)o_base * MAXD + tid];
    }
    __syncthreads();

    float4 acc = make_float4(0.f, 0.f, 0.f, 0.f);
    #pragma unroll
    for (int d = 0; d < MAXD; d++) {
        const int   idx = s_idx[ol * MAXD + d];
        const float m   = s_msk[ol * MAXD + d];
        const float4 v  = *reinterpret_cast<const float4*>(
            g_xt + (size_t)idx * NC + q * 4);
        acc.x += m * v.x;
        acc.y += m * v.y;
        acc.z += m * v.z;
        acc.w += m * v.w;
    }
    *reinterpret_cast<float4*>(
        g_pooled + (size_t)(o_base + ol) * NC + q * 4) = acc;
}

// ---------------------------------------------------------------------------
// Kernel 3: epilogue matmul + bias.
//   y[n][d][o] = sum_c pooled[o][n*32+c] * weight[c][d] + bias[d][o]
// Block: o-tile of 32, 256 threads. Warp = one n, lanes = o (coalesced out).
// pooled row cached in 32 regs; weight read as broadcast LDS.128.
// ---------------------------------------------------------------------------
__global__ __launch_bounds__(256) void epilogue_kernel(
    const float* __restrict__ weight,  // [INC][OUTC]
    const float* __restrict__ bias,    // [OUTC][OUTN]
    float*       __restrict__ y)       // [NBATCH][OUTC][OUTN]
{
    __shared__ float s_p[32][257];     // padded: o-column reads conflict-free
    __shared__ float s_w[INC * OUTC];  // 4 KB

    const int tid    = threadIdx.x;
    const int o_base = blockIdx.x * 32;

    #pragma unroll
    for (int k = tid; k < INC * OUTC; k += 256) s_w[k] = weight[k];

    // Load pooled tile [32][256] with float4 LDG, scalar STS.
    // lane map inside each 256-chunk: qq_low = t&7, row = (t&255)>>3 ->
    // warp covers 4 rows x 8 quads; STS bank (row + 4*qq_low + k) distinct.
    #pragma unroll
    for (int t = tid; t < 32 * 64; t += 256) {
        const int chunk = t >> 8;                 // 0..7
        const int within = t & 255;
        const int row = within >> 3;              // 0..31
        const int qq  = (within & 7) + 8 * chunk; // 0..63
        const float4 v = *reinterpret_cast<const float4*>(
            g_pooled + (size_t)(o_base + row) * NC + qq * 4);
        s_p[row][qq * 4 + 0] = v.x;
        s_p[row][qq * 4 + 1] = v.y;
        s_p[row][qq * 4 + 2] = v.z;
        s_p[row][qq * 4 + 3] = v.w;
    }
    __syncthreads();

    const int o_lane = tid & 31;
    const int n      = tid >> 5;      // 0..7
    const int o      = o_base + o_lane;

    // Cache this thread's pooled row segment in registers.
    float p[INC];
    #pragma unroll
    for (int c = 0; c < INC; c++) p[c] = s_p[o_lane][n * INC + c];

    #pragma unroll
    for (int dg = 0; dg < 8; dg++) {
        float4 acc = make_float4(0.f, 0.f, 0.f, 0.f);
        #pragma unroll
        for (int c = 0; c < INC; c++) {
            // broadcast LDS.128: all lanes same address
            const float4 w = *reinterpret_cast<const float4*>(
                s_w + c * OUTC + dg * 4);
            acc.x += p[c] * w.x;
            acc.y += p[c] * w.y;
            acc.z += p[c] * w.z;
            acc.w += p[c] * w.w;
        }
        const int d0 = dg * 4;
        y[(size_t)n * (OUTC * OUTN) + (size_t)(d0 + 0) * OUTN + o] =
            acc.x + bias[(size_t)(d0 + 0) * OUTN + o];
        y[(size_t)n * (OUTC * OUTN) + (size_t)(d0 + 1) * OUTN + o] =
            acc.y + bias[(size_t)(d0 + 1) * OUTN + o];
        y[(size_t)n * (OUTC * OUTN) + (size_t)(d0 + 2) * OUTN + o] =
            acc.z + bias[(size_t)(d0 + 2) * OUTN + o];
        y[(size_t)n * (OUTC * OUTN) + (size_t)(d0 + 3) * OUTN + o] =
            acc.w + bias[(size_t)(d0 + 3) * OUTN + o];
    }
}

// ---------------------------------------------------------------------------
// Launch
// ---------------------------------------------------------------------------
extern "C" void kernel_launch(void* const* d_in, const int* in_sizes, int n_in,
                              void* d_out, int out_size) {
    const float* x      = (const float*)d_in[0];
    const int*   A      = (const int*)  d_in[1];
    const float* mask   = (const float*)d_in[2];
    const float* weight = (const float*)d_in[3];
    const float* bias   = (const float*)d_in[4];
    float*       y      = (float*)d_out;

    {
        dim3 grid((INN + TI - 1) / TI, NC / 32);   // 391 x 8
        transpose_kernel<<<grid, 256>>>(x);
    }
    {
        dim3 grid(OUTN / 4);                        // 2048
        gather_kernel<<<grid, 256>>>(A, mask);
    }
    {
        dim3 grid(OUTN / 32);                       // 256
        epilogue_kernel<<<grid, 256>>>(weight, bias, y);
    }
}